// round 6
// baseline (speedup 1.0000x reference)
#include <cuda_runtime.h>
#include <cstddef>

#define BATCHN 128
#define SEQN   2048
#define FEATN  64
#define UNITSN 64
#define GATESN 256
#define OUTDN  6
#define NTHREADS 512

__device__ __forceinline__ float rcp_f(float x) {
    float r; asm("rcp.approx.f32 %0, %1;" : "=f"(r) : "f"(x)); return r;
}
__device__ __forceinline__ float ex2_f(float x) {
    float r; asm("ex2.approx.f32 %0, %1;" : "=f"(r) : "f"(x)); return r;
}

// Thread map (512 threads): warp w (0..15), lane l:
//   half = l>>4      k-range: half*32 .. half*32+31
//   g    = (l>>2)&3  gate i,f,g,o
//   uin  = l&3
//   u    = w*4 + uin (unit 0..63)
//   j    = g*64 + u  (logical gate column)
//   p    = u*4 + g   (gate-interleaved column -> conflict-free banks)
// Smem weights k-quad interleaved: Wq[(k>>2)*1024 + p*4 + (k&3)], so one
// LDS.128 yields 4 consecutive k values for column p (feeds 4 scalar FMAs).
// NOTE: accumulators start at 0; bias is added AFTER the cross-half
// shfl_xor reduce (adding it before double-counts it — R4 bug).
__global__ void __launch_bounds__(NTHREADS, 1)
lstm_scan_kernel(const float* __restrict__ x,
                 const float* __restrict__ W0, const float* __restrict__ U0,
                 const float* __restrict__ b0,
                 const float* __restrict__ W1, const float* __restrict__ U1,
                 const float* __restrict__ b1,
                 const float* __restrict__ Wf, const float* __restrict__ bf,
                 const float* __restrict__ Wo, const float* __restrict__ bo,
                 float* __restrict__ out)
{
    extern __shared__ float sm[];
    float* W0q = sm;                      // 16384 floats
    float* U0q = W0q + FEATN * GATESN;    // 16384
    float* h0s = U0q + FEATN * GATESN;    // 2*64 (double buffered)
    float* h1s = h0s + 2 * UNITSN;        // 2*64
    float* h2s = h1s + 2 * UNITSN;        // 2*64
    float* xs  = h2s + 2 * UNITSN;        // 2*64
    float* fs  = xs  + 2 * FEATN;         // 64

    const int b    = blockIdx.x;
    const int tid  = threadIdx.x;
    const int w    = tid >> 5;
    const int l    = tid & 31;
    const int half = l >> 4;
    const int g    = (l >> 2) & 3;
    const int uin  = l & 3;
    const int u    = (w << 2) | uin;
    const int j    = (g << 6) | u;
    const int p    = (u << 2) | g;
    const int kb   = half << 5;           // 0 or 32

    // Stage W0/U0 into swizzled k-quad layout (coalesced global reads)
    for (int i = tid; i < FEATN * GATESN; i += NTHREADS) {
        int k  = i >> 8;
        int jj = i & 255;
        int pp = ((jj & 63) << 2) | (jj >> 6);
        int d  = ((k >> 2) << 10) + (pp << 2) + (k & 3);
        W0q[d] = W0[i];
        U0q[d] = U0[i];
    }

    // W1/U1 column j, this thread's k-half (32 + 32 regs)
    float w1r[32], u1r[32];
#pragma unroll
    for (int k = 0; k < 32; k++) {
        w1r[k] = W1[(kb + k) * GATESN + j];
        u1r[k] = U1[(kb + k) * GATESN + j];
    }
    const float b0r = b0[j];
    const float b1r = b1[j];

    if (tid < UNITSN) {
        h0s[tid] = 0.f; h0s[UNITSN + tid] = 0.f;
        h1s[tid] = 0.f; h1s[UNITSN + tid] = 0.f;
        h2s[tid] = 0.f; h2s[UNITSN + tid] = 0.f;
    }
    const float* xb = x + (size_t)b * SEQN * FEATN;
    const bool xldr = (tid < FEATN);
    if (xldr) xs[tid] = xb[tid];

    // activation constants (gate 2 = tanh candidate)
    const float kpre = (g == 2) ? -2.8853900817779268f : -1.4426950408889634f;
    const float kmul = (g == 2) ?  2.0f : 1.0f;
    const float kadd = (g == 2) ? -1.0f : 0.0f;
    const unsigned FULL = 0xffffffffu;

    const float* Wb = W0q + (half << 13) + (p << 2);  // + half*8*1024
    const float* Ub = U0q + (half << 13) + (p << 2);

    float c0 = 0.f, c1 = 0.f, c2 = 0.f;
    __syncthreads();

    int cur = 0;
    for (int t = 0; t < SEQN; t++) {
        const int nxt = cur ^ 1;

        // Prefetch next timestep's x (clamped at the tail; value unused at t=T-1)
        float xn = 0.f;
        if (xldr) {
            int tn = (t + 1 < SEQN) ? (t + 1) : t;
            xn = __ldg(xb + (size_t)tn * FEATN + tid);
        }

        // ---------------- layer 0: z = x*W0 + h0*U0 + b0 ----------------
        {
            const float* xv = xs  + cur * FEATN  + kb;
            const float* hv = h0s + cur * UNITSN + kb;
            float a0 = 0.f, a1 = 0.f, a2 = 0.f, a3 = 0.f;
#pragma unroll
            for (int q = 0; q < 8; q++) {
                float4 wq = *reinterpret_cast<const float4*>(Wb + (q << 10));
                float4 uq = *reinterpret_cast<const float4*>(Ub + (q << 10));
                float4 xq = *reinterpret_cast<const float4*>(xv + (q << 2));
                float4 hq = *reinterpret_cast<const float4*>(hv + (q << 2));
                a0 = fmaf(xq.x, wq.x, a0);
                a1 = fmaf(xq.y, wq.y, a1);
                a2 = fmaf(xq.z, wq.z, a2);
                a3 = fmaf(xq.w, wq.w, a3);
                a0 = fmaf(hq.x, uq.x, a0);
                a1 = fmaf(hq.y, uq.y, a1);
                a2 = fmaf(hq.z, uq.z, a2);
                a3 = fmaf(hq.w, uq.w, a3);
            }
            float s = (a0 + a1) + (a2 + a3);
            s += __shfl_xor_sync(FULL, s, 16);
            float z   = s + b0r;
            float act = fmaf(rcp_f(1.0f + ex2_f(z * kpre)), kmul, kadd);
            float vi = __shfl_sync(FULL, act, uin);
            float vf = __shfl_sync(FULL, act, uin + 4);
            float vg = __shfl_sync(FULL, act, uin + 8);
            float vo = __shfl_sync(FULL, act, uin + 12);
            c0 = fmaf(vf, c0, vi * vg);
            float e  = ex2_f(c0 * -2.8853900817779268f);
            float hn = vo * fmaf(2.0f, rcp_f(1.0f + e), -1.0f);
            if (l < 4) h0s[nxt * UNITSN + u] = hn;
        }
        __syncthreads();

        // ---------------- layer 1: z = h0_new*W1 + h1*U1 + b1 ----------------
        {
            const float* iv = h0s + nxt * UNITSN + kb;
            const float* hv = h1s + cur * UNITSN + kb;
            float a0 = 0.f, a1 = 0.f, a2 = 0.f, a3 = 0.f;
#pragma unroll
            for (int q = 0; q < 8; q++) {
                float4 iq = *reinterpret_cast<const float4*>(iv + (q << 2));
                float4 hq = *reinterpret_cast<const float4*>(hv + (q << 2));
                a0 = fmaf(iq.x, w1r[4 * q + 0], a0);
                a1 = fmaf(iq.y, w1r[4 * q + 1], a1);
                a2 = fmaf(iq.z, w1r[4 * q + 2], a2);
                a3 = fmaf(iq.w, w1r[4 * q + 3], a3);
                a0 = fmaf(hq.x, u1r[4 * q + 0], a0);
                a1 = fmaf(hq.y, u1r[4 * q + 1], a1);
                a2 = fmaf(hq.z, u1r[4 * q + 2], a2);
                a3 = fmaf(hq.w, u1r[4 * q + 3], a3);
            }
            float s = (a0 + a1) + (a2 + a3);
            s += __shfl_xor_sync(FULL, s, 16);
            float z   = s + b1r;
            float act = fmaf(rcp_f(1.0f + ex2_f(z * kpre)), kmul, kadd);
            float vi = __shfl_sync(FULL, act, uin);
            float vf = __shfl_sync(FULL, act, uin + 4);
            float vg = __shfl_sync(FULL, act, uin + 8);
            float vo = __shfl_sync(FULL, act, uin + 12);
            c1 = fmaf(vf, c1, vi * vg);
            float e  = ex2_f(c1 * -2.8853900817779268f);
            float hn = vo * fmaf(2.0f, rcp_f(1.0f + e), -1.0f);
            if (l < 4) h1s[nxt * UNITSN + u] = hn;
        }
        __syncthreads();

        // ------- layer 2: z = h1_new*W1 + h2*U1 + b1 (weights shared) -------
        {
            const float* iv = h1s + nxt * UNITSN + kb;
            const float* hv = h2s + cur * UNITSN + kb;
            float a0 = 0.f, a1 = 0.f, a2 = 0.f, a3 = 0.f;
#pragma unroll
            for (int q = 0; q < 8; q++) {
                float4 iq = *reinterpret_cast<const float4*>(iv + (q << 2));
                float4 hq = *reinterpret_cast<const float4*>(hv + (q << 2));
                a0 = fmaf(iq.x, w1r[4 * q + 0], a0);
                a1 = fmaf(iq.y, w1r[4 * q + 1], a1);
                a2 = fmaf(iq.z, w1r[4 * q + 2], a2);
                a3 = fmaf(iq.w, w1r[4 * q + 3], a3);
                a0 = fmaf(hq.x, u1r[4 * q + 0], a0);
                a1 = fmaf(hq.y, u1r[4 * q + 1], a1);
                a2 = fmaf(hq.z, u1r[4 * q + 2], a2);
                a3 = fmaf(hq.w, u1r[4 * q + 3], a3);
            }
            float s = (a0 + a1) + (a2 + a3);
            s += __shfl_xor_sync(FULL, s, 16);
            float z   = s + b1r;
            float act = fmaf(rcp_f(1.0f + ex2_f(z * kpre)), kmul, kadd);
            float vi = __shfl_sync(FULL, act, uin);
            float vf = __shfl_sync(FULL, act, uin + 4);
            float vg = __shfl_sync(FULL, act, uin + 8);
            float vo = __shfl_sync(FULL, act, uin + 12);
            c2 = fmaf(vf, c2, vi * vg);
            float e  = ex2_f(c2 * -2.8853900817779268f);
            float hn = vo * fmaf(2.0f, rcp_f(1.0f + e), -1.0f);
            if (l < 4) h2s[nxt * UNITSN + u] = hn;
        }
        if (xldr) xs[nxt * FEATN + tid] = xn;
        __syncthreads();

        cur = nxt;
    }

    // ---------------- dense head: relu(h2*Wf+bf) * Wo + bo ----------------
    if (tid < UNITSN) {
        float a = bf[tid];
#pragma unroll 8
        for (int k = 0; k < UNITSN; k++)
            a = fmaf(h2s[cur * UNITSN + k], Wf[k * 64 + tid], a);
        fs[tid] = fmaxf(a, 0.f);
    }
    __syncthreads();
    if (tid < OUTDN) {
        float a = bo[tid];
#pragma unroll 8
        for (int k = 0; k < UNITSN; k++)
            a = fmaf(fs[k], Wo[k * OUTDN + tid], a);
        out[b * OUTDN + tid] = a;
    }
}

extern "C" void kernel_launch(void* const* d_in, const int* in_sizes, int n_in,
                              void* d_out, int out_size)
{
    (void)in_sizes; (void)n_in; (void)out_size;
    const float* x  = (const float*)d_in[0];
    const float* W0 = (const float*)d_in[1];
    const float* U0 = (const float*)d_in[2];
    const float* b0 = (const float*)d_in[3];
    const float* W1 = (const float*)d_in[4];
    const float* U1 = (const float*)d_in[5];
    const float* b1 = (const float*)d_in[6];
    const float* Wf = (const float*)d_in[7];
    const float* bf = (const float*)d_in[8];
    const float* Wo = (const float*)d_in[9];
    const float* bo = (const float*)d_in[10];
    float* out = (float*)d_out;

    const size_t smem_bytes =
        (size_t)(2 * FEATN * GATESN + 6 * UNITSN + 2 * FEATN + UNITSN) * sizeof(float);
    cudaFuncSetAttribute(lstm_scan_kernel,
                         cudaFuncAttributeMaxDynamicSharedMemorySize,
                         (int)smem_bytes);
    lstm_scan_kernel<<<BATCHN, NTHREADS, smem_bytes>>>(x, W0, U0, b0, W1, U1, b1,
                                                       Wf, bf, Wo, bo, out);
}